// round 10
// baseline (speedup 1.0000x reference)
#include <cuda_runtime.h>
#include <cuda_fp16.h>
#include <mma.h>
#include <math.h>
#include <float.h>

using namespace nvcuda;

#define NN 50000
#define EE 800000
#define ET (EE + NN)
#define SCAN_B 49   // ceil(50000/1024)

// ---------------- scratch ---------------------------------------------------
__device__ __half g_h1[NN * 128];
__device__ __half g_h2[NN * 128];
__device__ __half g_agg1[NN * 128];   // layer-1 output, fp16 (GEMM input)
__device__ __half g_W1h[128 * 128];
__device__ __half g_W2h[128 * 128];
__device__ float  g_as1[NN * 4];
__device__ float  g_ad1[NN * 4];
__device__ float  g_as2[NN];
__device__ float  g_ad2[NN];
__device__ int    g_deg[NN];
__device__ int    g_scan[SCAN_B * 1024];
__device__ int    g_bsum[SCAN_B];
__device__ int    g_boff[SCAN_B];
__device__ int    g_rowptr[NN + 1];
__device__ int    g_fill[NN];
__device__ int2   g_cd[ET];           // packed (src, dst)
__device__ float  g_w1[ET * 4];       // per-edge exp weights, layer1
__device__ float  g_w2[ET];           // layer2

__device__ __forceinline__ float lrelu(float x) { return x > 0.f ? x : 0.2f * x; }
__device__ __forceinline__ float elu(float x)   { return x > 0.f ? x : expm1f(x); }

// ---------------- CSR build -------------------------------------------------
__global__ void k_zero() {
    int i = blockIdx.x * blockDim.x + threadIdx.x;
    if (i < NN) g_deg[i] = 0;
}

__global__ void k_count(const int* __restrict__ ei) {
    int e = blockIdx.x * blockDim.x + threadIdx.x;
    if (e >= ET) return;
    int d = (e < EE) ? ei[EE + e] : (e - EE);
    atomicAdd(&g_deg[d], 1);
}

__global__ void k_scan_part() {
    __shared__ int sh[1024];
    int tid = threadIdx.x;
    int i = blockIdx.x * 1024 + tid;
    int v = (i < NN) ? g_deg[i] : 0;
    sh[tid] = v;
    __syncthreads();
#pragma unroll
    for (int off = 1; off < 1024; off <<= 1) {
        int t = (tid >= off) ? sh[tid - off] : 0;
        __syncthreads();
        sh[tid] += t;
        __syncthreads();
    }
    g_scan[i] = sh[tid];
    if (tid == 1023) g_bsum[blockIdx.x] = sh[tid];
}

// parallel top-level scan over SCAN_B block sums (64 threads)
__global__ void k_scan_top() {
    __shared__ int sh[64];
    int t = threadIdx.x;
    int v = (t < SCAN_B) ? g_bsum[t] : 0;
    sh[t] = v;
    __syncthreads();
#pragma unroll
    for (int off = 1; off < 64; off <<= 1) {
        int u = (t >= off) ? sh[t - off] : 0;
        __syncthreads();
        sh[t] += u;
        __syncthreads();
    }
    if (t < SCAN_B) g_boff[t] = sh[t] - v;   // exclusive
}

__global__ void k_rowptr() {
    int i = blockIdx.x * blockDim.x + threadIdx.x;
    if (i >= NN) return;
    int incl = g_scan[i] + g_boff[i >> 10];
    g_rowptr[i + 1] = incl;
    g_fill[i] = incl - g_deg[i];
    if (i == 0) g_rowptr[0] = 0;
}

__global__ void k_fill(const int* __restrict__ ei) {
    int e = blockIdx.x * blockDim.x + threadIdx.x;
    if (e >= ET) return;
    int s, d;
    if (e < EE) { s = ei[e]; d = ei[EE + e]; } else { s = e - EE; d = s; }
    int pos = atomicAdd(&g_fill[d], 1);
    g_cd[pos] = make_int2(s, d);
}

// ---------------- W fp32 -> fp16 (both layers, one launch) -------------------
__global__ void k_convW(const float* __restrict__ W1, const float* __restrict__ W2) {
    int i = blockIdx.x * blockDim.x + threadIdx.x;
    if (i < 128 * 128) {
        g_W1h[i] = __float2half(W1[i]);
        g_W2h[i] = __float2half(W2[i]);
    }
}

// ---------------- tensor-core GEMM [NN,128]@[128,128] -----------------------
// block: 64 rows x 128 cols, 512 threads (16 warps: 4 row-tiles x 4 col-pairs)
// LAYER 0: X = Xext fp32 (convert), W = g_W1h, H = g_h1, alpha -> as1/ad1 (4 heads)
// LAYER 1: X = g_agg1 fp16,         W = g_W2h, H = g_h2, alpha -> as2/ad2 (1 head)
template <int LAYER>
__global__ void __launch_bounds__(512) k_gemm_tc(const float* __restrict__ Xext,
                                                 const float* __restrict__ asrc,
                                                 const float* __restrict__ adst) {
    __shared__ __align__(16) char smem[49152];
    __half* sA = (__half*)smem;              // 64*128*2  = 16384 B
    __half* sW = (__half*)(smem + 16384);    // 128*128*2 = 32768 B
    float*  sC = (float*)smem;               // 64*128*4  = 32768 B (reused after MMA)

    const __half* __restrict__ Wh = (LAYER == 0) ? g_W1h : g_W2h;
    __half* __restrict__ H = (LAYER == 0) ? g_h1 : g_h2;

    int tid = threadIdx.x;
    int row0 = blockIdx.x * 64;

    // stage W: 16384 halves = 2048 uint4; 512 threads x 4
    {
        const uint4* src = (const uint4*)Wh;
        uint4* dst = (uint4*)sW;
#pragma unroll
        for (int j = 0; j < 4; j++) dst[tid + j * 512] = src[tid + j * 512];
    }
    // stage A (convert if fp32)
    if (LAYER == 0) {
        // 64 rows x 128 cols: 8192 elems, float4 loads: 2048 x float4; 512 thr x 4
#pragma unroll
        for (int j = 0; j < 4; j++) {
            int idx = tid + j * 512;          // float4 index
            int r = idx >> 5, c4 = idx & 31;  // 32 float4 per row
            int row = row0 + r;
            float4 v = make_float4(0.f, 0.f, 0.f, 0.f);
            if (row < NN) v = ((const float4*)Xext)[row * 32 + c4];
            __half2 h0 = __floats2half2_rn(v.x, v.y);
            __half2 h1 = __floats2half2_rn(v.z, v.w);
            *(__half2*)(sA + r * 128 + c4 * 4)     = h0;
            *(__half2*)(sA + r * 128 + c4 * 4 + 2) = h1;
        }
    } else {
        // fp16 input: 8192 halves = 1024 uint4; 512 thr x 2
#pragma unroll
        for (int j = 0; j < 2; j++) {
            int idx = tid + j * 512;          // uint4 index (8 halves)
            int r = idx >> 4, c8 = idx & 15;
            int row = row0 + r;
            uint4 v = make_uint4(0u, 0u, 0u, 0u);
            if (row < NN) v = ((const uint4*)g_agg1)[row * 16 + c8];
            ((uint4*)sA)[idx] = v;
        }
    }
    __syncthreads();

    // MMA: warp (wr, wc): rows [wr*16,+16), cols [wc*32,+32)
    int wid = tid >> 5;
    int wr = wid >> 2, wc = wid & 3;

    wmma::fragment<wmma::accumulator, 16, 16, 16, float> c0, c1;
    wmma::fill_fragment(c0, 0.f);
    wmma::fill_fragment(c1, 0.f);

#pragma unroll
    for (int k = 0; k < 8; k++) {
        wmma::fragment<wmma::matrix_a, 16, 16, 16, __half, wmma::row_major> af;
        wmma::fragment<wmma::matrix_b, 16, 16, 16, __half, wmma::row_major> bf0, bf1;
        wmma::load_matrix_sync(af, sA + wr * 16 * 128 + k * 16, 128);
        wmma::load_matrix_sync(bf0, sW + k * 16 * 128 + wc * 32, 128);
        wmma::load_matrix_sync(bf1, sW + k * 16 * 128 + wc * 32 + 16, 128);
        wmma::mma_sync(c0, af, bf0, c0);
        wmma::mma_sync(c1, af, bf1, c1);
    }
    __syncthreads();   // done with sA/sW; reuse as sC

    wmma::store_matrix_sync(sC + wr * 16 * 128 + wc * 32,      c0, 128, wmma::mem_row_major);
    wmma::store_matrix_sync(sC + wr * 16 * 128 + wc * 32 + 16, c1, 128, wmma::mem_row_major);
    __syncthreads();

    // epilogue: 8 threads per row, 16 cols each
    {
        int r = tid >> 3;
        int t8 = tid & 7;
        int c0i = t8 * 16;
        int row = row0 + r;
        if (row < NN) {
            float v[16];
#pragma unroll
            for (int j = 0; j < 16; j++) v[j] = sC[r * 128 + c0i + j];

            // h store (fp16, 16 halves = 2 x uint4)
            uint4 p0, p1;
            __half2 hh[8];
#pragma unroll
            for (int j = 0; j < 8; j++) hh[j] = __floats2half2_rn(v[2 * j], v[2 * j + 1]);
            p0 = make_uint4(*(unsigned*)&hh[0], *(unsigned*)&hh[1], *(unsigned*)&hh[2], *(unsigned*)&hh[3]);
            p1 = make_uint4(*(unsigned*)&hh[4], *(unsigned*)&hh[5], *(unsigned*)&hh[6], *(unsigned*)&hh[7]);
            ((uint4*)H)[row * 16 + t8 * 2]     = p0;
            ((uint4*)H)[row * 16 + t8 * 2 + 1] = p1;

            float s = 0.f, d = 0.f;
#pragma unroll
            for (int j = 0; j < 16; j++) {
                s += v[j] * asrc[c0i + j];
                d += v[j] * adst[c0i + j];
            }
            if (LAYER == 0) {
                // head = t8>>1; pair-reduce neighbors
                s += __shfl_xor_sync(0xffffffffu, s, 1);
                d += __shfl_xor_sync(0xffffffffu, d, 1);
                if ((t8 & 1) == 0) {
                    g_as1[row * 4 + (t8 >> 1)] = s;
                    g_ad1[row * 4 + (t8 >> 1)] = d;
                }
            } else {
#pragma unroll
                for (int off = 1; off < 8; off <<= 1) {
                    s += __shfl_xor_sync(0xffffffffu, s, off);
                    d += __shfl_xor_sync(0xffffffffu, d, off);
                }
                if (t8 == 0) { g_as2[row] = s; g_ad2[row] = d; }
            }
        }
    }
}

// ---------------- edge-parallel exp weights (no max shift) ------------------
__global__ void k_edgew1() {
    int e = blockIdx.x * blockDim.x + threadIdx.x;
    if (e >= ET) return;
    int2 cd = g_cd[e];
    float4 a = ((const float4*)g_as1)[cd.x];
    float4 b = ((const float4*)g_ad1)[cd.y];
    float4 w;
    w.x = __expf(lrelu(a.x + b.x));
    w.y = __expf(lrelu(a.y + b.y));
    w.z = __expf(lrelu(a.z + b.z));
    w.w = __expf(lrelu(a.w + b.w));
    ((float4*)g_w1)[e] = w;
}

__global__ void k_edgew2() {
    int e = blockIdx.x * blockDim.x + threadIdx.x;
    if (e >= ET) return;
    int2 cd = g_cd[e];
    g_w2[e] = __expf(lrelu(g_as2[cd.x] + g_ad2[cd.y]));
}

// ---------------- node aggregation, layer 1 (4 heads) -----------------------
__global__ void k_node1(const float* __restrict__ b1) {
    int w = (blockIdx.x * blockDim.x + threadIdx.x) >> 5;
    int lane = threadIdx.x & 31;
    if (w >= NN) return;
    int beg = g_rowptr[w], end = g_rowptr[w + 1];
    int hd = lane >> 3;

    float ws = 0.f;
    float4 acc = make_float4(0.f, 0.f, 0.f, 0.f);

    int i = beg;
    for (; i + 4 <= end; i += 4) {
        int s0 = g_cd[i].x, s1 = g_cd[i + 1].x, s2 = g_cd[i + 2].x, s3 = g_cd[i + 3].x;
        float4 w0 = ((const float4*)g_w1)[i];
        float4 w1 = ((const float4*)g_w1)[i + 1];
        float4 w2 = ((const float4*)g_w1)[i + 2];
        float4 w3 = ((const float4*)g_w1)[i + 3];
        uint2 r0 = ((const uint2*)g_h1)[s0 * 32 + lane];
        uint2 r1 = ((const uint2*)g_h1)[s1 * 32 + lane];
        uint2 r2 = ((const uint2*)g_h1)[s2 * 32 + lane];
        uint2 r3 = ((const uint2*)g_h1)[s3 * 32 + lane];
        float wh0 = (hd == 0) ? w0.x : (hd == 1) ? w0.y : (hd == 2) ? w0.z : w0.w;
        float wh1 = (hd == 0) ? w1.x : (hd == 1) ? w1.y : (hd == 2) ? w1.z : w1.w;
        float wh2 = (hd == 0) ? w2.x : (hd == 1) ? w2.y : (hd == 2) ? w2.z : w2.w;
        float wh3 = (hd == 0) ? w3.x : (hd == 1) ? w3.y : (hd == 2) ? w3.z : w3.w;
        ws += wh0 + wh1 + wh2 + wh3;
        float2 a0 = __half22float2(*reinterpret_cast<__half2*>(&r0.x));
        float2 b0 = __half22float2(*reinterpret_cast<__half2*>(&r0.y));
        float2 a1 = __half22float2(*reinterpret_cast<__half2*>(&r1.x));
        float2 b1v = __half22float2(*reinterpret_cast<__half2*>(&r1.y));
        float2 a2 = __half22float2(*reinterpret_cast<__half2*>(&r2.x));
        float2 b2v = __half22float2(*reinterpret_cast<__half2*>(&r2.y));
        float2 a3 = __half22float2(*reinterpret_cast<__half2*>(&r3.x));
        float2 b3v = __half22float2(*reinterpret_cast<__half2*>(&r3.y));
        acc.x += wh0 * a0.x + wh1 * a1.x + wh2 * a2.x + wh3 * a3.x;
        acc.y += wh0 * a0.y + wh1 * a1.y + wh2 * a2.y + wh3 * a3.y;
        acc.z += wh0 * b0.x + wh1 * b1v.x + wh2 * b2v.x + wh3 * b3v.x;
        acc.w += wh0 * b0.y + wh1 * b1v.y + wh2 * b2v.y + wh3 * b3v.y;
    }
    for (; i < end; i++) {
        int s = g_cd[i].x;
        float4 wv = ((const float4*)g_w1)[i];
        float wh = (hd == 0) ? wv.x : (hd == 1) ? wv.y : (hd == 2) ? wv.z : wv.w;
        ws += wh;
        uint2 raw = ((const uint2*)g_h1)[s * 32 + lane];
        float2 f01 = __half22float2(*reinterpret_cast<__half2*>(&raw.x));
        float2 f23 = __half22float2(*reinterpret_cast<__half2*>(&raw.y));
        acc.x += wh * f01.x;
        acc.y += wh * f01.y;
        acc.z += wh * f23.x;
        acc.w += wh * f23.y;
    }

    float inv = 1.f / (ws + 1e-16f);
    float4 bv = ((const float4*)b1)[lane];
    float o0 = elu(acc.x * inv + bv.x);
    float o1 = elu(acc.y * inv + bv.y);
    float o2 = elu(acc.z * inv + bv.z);
    float o3 = elu(acc.w * inv + bv.w);
    __half2 p0 = __floats2half2_rn(o0, o1);
    __half2 p1 = __floats2half2_rn(o2, o3);
    uint2 pk = make_uint2(*(unsigned*)&p0, *(unsigned*)&p1);
    ((uint2*)g_agg1)[w * 32 + lane] = pk;
}

// ---------------- node aggregation, layer 2 (1 head) ------------------------
__global__ void k_node2(const float* __restrict__ b2, float* __restrict__ out) {
    int w = (blockIdx.x * blockDim.x + threadIdx.x) >> 5;
    int lane = threadIdx.x & 31;
    if (w >= NN) return;
    int beg = g_rowptr[w], end = g_rowptr[w + 1];

    float ws = 0.f;
    float4 acc = make_float4(0.f, 0.f, 0.f, 0.f);

    int i = beg;
    for (; i + 4 <= end; i += 4) {
        int s0 = g_cd[i].x, s1 = g_cd[i + 1].x, s2 = g_cd[i + 2].x, s3 = g_cd[i + 3].x;
        float w0 = g_w2[i], w1 = g_w2[i + 1], w2 = g_w2[i + 2], w3 = g_w2[i + 3];
        uint2 r0 = ((const uint2*)g_h2)[s0 * 32 + lane];
        uint2 r1 = ((const uint2*)g_h2)[s1 * 32 + lane];
        uint2 r2 = ((const uint2*)g_h2)[s2 * 32 + lane];
        uint2 r3 = ((const uint2*)g_h2)[s3 * 32 + lane];
        ws += w0 + w1 + w2 + w3;
        float2 a0 = __half22float2(*reinterpret_cast<__half2*>(&r0.x));
        float2 b0 = __half22float2(*reinterpret_cast<__half2*>(&r0.y));
        float2 a1 = __half22float2(*reinterpret_cast<__half2*>(&r1.x));
        float2 b1v = __half22float2(*reinterpret_cast<__half2*>(&r1.y));
        float2 a2 = __half22float2(*reinterpret_cast<__half2*>(&r2.x));
        float2 b2v = __half22float2(*reinterpret_cast<__half2*>(&r2.y));
        float2 a3 = __half22float2(*reinterpret_cast<__half2*>(&r3.x));
        float2 b3v = __half22float2(*reinterpret_cast<__half2*>(&r3.y));
        acc.x += w0 * a0.x + w1 * a1.x + w2 * a2.x + w3 * a3.x;
        acc.y += w0 * a0.y + w1 * a1.y + w2 * a2.y + w3 * a3.y;
        acc.z += w0 * b0.x + w1 * b1v.x + w2 * b2v.x + w3 * b3v.x;
        acc.w += w0 * b0.y + w1 * b1v.y + w2 * b2v.y + w3 * b3v.y;
    }
    for (; i < end; i++) {
        int s = g_cd[i].x;
        float wv = g_w2[i];
        ws += wv;
        uint2 raw = ((const uint2*)g_h2)[s * 32 + lane];
        float2 f01 = __half22float2(*reinterpret_cast<__half2*>(&raw.x));
        float2 f23 = __half22float2(*reinterpret_cast<__half2*>(&raw.y));
        acc.x += wv * f01.x;
        acc.y += wv * f01.y;
        acc.z += wv * f23.x;
        acc.w += wv * f23.y;
    }

    float inv = 1.f / (ws + 1e-16f);
    float4 bv = ((const float4*)b2)[lane];
    float4 o;
    o.x = elu(acc.x * inv + bv.x);
    o.y = elu(acc.y * inv + bv.y);
    o.z = elu(acc.z * inv + bv.z);
    o.w = elu(acc.w * inv + bv.w);
    ((float4*)out)[w * 32 + lane] = o;
}

// ---------------- host launch ------------------------------------------------
extern "C" void kernel_launch(void* const* d_in, const int* in_sizes, int n_in,
                              void* d_out, int out_size) {
    const float* x    = (const float*)d_in[0];
    const int*   ei   = (const int*)  d_in[1];
    const float* W1   = (const float*)d_in[2];
    const float* a_s1 = (const float*)d_in[3];
    const float* a_d1 = (const float*)d_in[4];
    const float* b1   = (const float*)d_in[5];
    const float* W2   = (const float*)d_in[6];
    const float* a_s2 = (const float*)d_in[7];
    const float* a_d2 = (const float*)d_in[8];
    const float* b2   = (const float*)d_in[9];
    float* out = (float*)d_out;

    const int EB = (ET + 255) / 256;
    const int NB = (NN + 255) / 256;
    const int WARPB = (NN * 32 + 255) / 256;
    const int GB = (NN + 63) / 64;

    // CSR build + W conversion
    k_zero<<<NB, 256>>>();
    k_count<<<EB, 256>>>(ei);
    k_convW<<<64, 256>>>(W1, W2);
    k_scan_part<<<SCAN_B, 1024>>>();
    k_scan_top<<<1, 64>>>();
    k_rowptr<<<NB, 256>>>();
    k_fill<<<EB, 256>>>(ei);

    // layer 1
    k_gemm_tc<0><<<GB, 512>>>(x, a_s1, a_d1);
    k_edgew1<<<EB, 256>>>();
    k_node1<<<WARPB, 256>>>(b1);

    // layer 2
    k_gemm_tc<1><<<GB, 512>>>(nullptr, a_s2, a_d2);
    k_edgew2<<<EB, 256>>>();
    k_node2<<<WARPB, 256>>>(b2, out);
}

// round 11
// speedup vs baseline: 1.1303x; 1.1303x over previous
#include <cuda_runtime.h>
#include <cuda_fp16.h>
#include <math.h>
#include <float.h>

#define NN 50000
#define EE 800000
#define ET (EE + NN)
#define SCAN_B 49   // ceil(50000/1024)

// ---------------- scratch ---------------------------------------------------
__device__ __half g_h1[NN * 128];
__device__ __half g_h2[NN * 128];
__device__ float  g_agg1[NN * 128];
__device__ float  g_as1[NN * 4];
__device__ float  g_ad1[NN * 4];
__device__ float  g_as2[NN];
__device__ float  g_ad2[NN];
__device__ int    g_deg[NN];
__device__ int    g_scan[SCAN_B * 1024];
__device__ int    g_bsum[SCAN_B];
__device__ int    g_boff[SCAN_B];
__device__ int    g_rowptr[NN + 1];
__device__ int    g_fill[NN];
__device__ int2   g_cd[ET];           // packed (src, dst)
__device__ float  g_w1[ET * 4];       // per-edge exp weights, layer1
__device__ float  g_w2[ET];           // layer2

__device__ __forceinline__ float lrelu(float x) { return x > 0.f ? x : 0.2f * x; }
__device__ __forceinline__ float elu(float x)   { return x > 0.f ? x : expm1f(x); }

// ---------------- CSR build -------------------------------------------------
__global__ void k_zero() {
    int i = blockIdx.x * blockDim.x + threadIdx.x;
    if (i < NN) g_deg[i] = 0;
}

__global__ void k_count(const int* __restrict__ ei) {
    int e = blockIdx.x * blockDim.x + threadIdx.x;
    if (e >= ET) return;
    int d = (e < EE) ? ei[EE + e] : (e - EE);
    atomicAdd(&g_deg[d], 1);
}

__global__ void k_scan_part() {
    __shared__ int sh[1024];
    int tid = threadIdx.x;
    int i = blockIdx.x * 1024 + tid;
    int v = (i < NN) ? g_deg[i] : 0;
    sh[tid] = v;
    __syncthreads();
#pragma unroll
    for (int off = 1; off < 1024; off <<= 1) {
        int t = (tid >= off) ? sh[tid - off] : 0;
        __syncthreads();
        sh[tid] += t;
        __syncthreads();
    }
    g_scan[i] = sh[tid];
    if (tid == 1023) g_bsum[blockIdx.x] = sh[tid];
}

// parallel top-level scan over SCAN_B block sums (64 threads)
__global__ void k_scan_top() {
    __shared__ int sh[64];
    int t = threadIdx.x;
    int v = (t < SCAN_B) ? g_bsum[t] : 0;
    sh[t] = v;
    __syncthreads();
#pragma unroll
    for (int off = 1; off < 64; off <<= 1) {
        int u = (t >= off) ? sh[t - off] : 0;
        __syncthreads();
        sh[t] += u;
        __syncthreads();
    }
    if (t < SCAN_B) g_boff[t] = sh[t] - v;   // exclusive
}

__global__ void k_rowptr() {
    int i = blockIdx.x * blockDim.x + threadIdx.x;
    if (i >= NN) return;
    int incl = g_scan[i] + g_boff[i >> 10];
    g_rowptr[i + 1] = incl;
    g_fill[i] = incl - g_deg[i];
    if (i == 0) g_rowptr[0] = 0;
}

__global__ void k_fill(const int* __restrict__ ei) {
    int e = blockIdx.x * blockDim.x + threadIdx.x;
    if (e >= ET) return;
    int s, d;
    if (e < EE) { s = ei[e]; d = ei[EE + e]; } else { s = e - EE; d = s; }
    int pos = atomicAdd(&g_fill[d], 1);
    g_cd[pos] = make_int2(s, d);
}

// ---------------- GEMM [NN,128]@[128,128], scalar FFMA, fp16 H store --------
// LAYER 0: X = x (arg), H = g_h1, alpha -> g_as1/g_ad1 (HEADS=4)
// LAYER 1: X = g_agg1,  H = g_h2, alpha -> g_as2/g_ad2 (HEADS=1)
template <int LAYER>
__global__ void __launch_bounds__(256) k_gemm(const float* __restrict__ Xext,
                       const float* __restrict__ W,
                       const float* __restrict__ asrc,
                       const float* __restrict__ adst) {
    const float* __restrict__ X = (LAYER == 0) ? Xext : g_agg1;
    __half* __restrict__ H = (LAYER == 0) ? g_h1 : g_h2;

    __shared__ float xs[64][128];
    int row0 = blockIdx.x * 64;

    for (int i = threadIdx.x; i < 64 * 32; i += 256) {
        int r = i >> 5, c4 = i & 31;
        int row = row0 + r;
        float4 v = make_float4(0.f, 0.f, 0.f, 0.f);
        if (row < NN) v = ((const float4*)X)[row * 32 + c4];
        *(float4*)(&xs[r][c4 * 4]) = v;
    }
    __syncthreads();

    int tc = threadIdx.x & 31;
    int tr = threadIdx.x >> 5;
    float acc[8][4];
#pragma unroll
    for (int r = 0; r < 8; r++)
#pragma unroll
        for (int j = 0; j < 4; j++) acc[r][j] = 0.f;

#pragma unroll 8
    for (int k = 0; k < 128; k++) {
        float4 w = ((const float4*)W)[k * 32 + tc];
#pragma unroll
        for (int r = 0; r < 8; r++) {
            float xv = xs[tr * 8 + r][k];
            acc[r][0] += xv * w.x;
            acc[r][1] += xv * w.y;
            acc[r][2] += xv * w.z;
            acc[r][3] += xv * w.w;
        }
    }

    float4 av = ((const float4*)asrc)[tc];
    float4 dv = ((const float4*)adst)[tc];

#pragma unroll
    for (int r = 0; r < 8; r++) {
        int row = row0 + tr * 8 + r;
        if (row >= NN) continue;
        __half2 p0 = __floats2half2_rn(acc[r][0], acc[r][1]);
        __half2 p1 = __floats2half2_rn(acc[r][2], acc[r][3]);
        ((__half2*)H)[row * 64 + tc * 2]     = p0;
        ((__half2*)H)[row * 64 + tc * 2 + 1] = p1;

        float s = acc[r][0] * av.x + acc[r][1] * av.y + acc[r][2] * av.z + acc[r][3] * av.w;
        float d = acc[r][0] * dv.x + acc[r][1] * dv.y + acc[r][2] * dv.z + acc[r][3] * dv.w;
        if (LAYER == 0) {
#pragma unroll
            for (int off = 4; off; off >>= 1) {
                s += __shfl_xor_sync(0xffffffffu, s, off);
                d += __shfl_xor_sync(0xffffffffu, d, off);
            }
            if ((tc & 7) == 0) {
                g_as1[row * 4 + (tc >> 3)] = s;
                g_ad1[row * 4 + (tc >> 3)] = d;
            }
        } else {
#pragma unroll
            for (int off = 16; off; off >>= 1) {
                s += __shfl_xor_sync(0xffffffffu, s, off);
                d += __shfl_xor_sync(0xffffffffu, d, off);
            }
            if (tc == 0) { g_as2[row] = s; g_ad2[row] = d; }
        }
    }
}

// ---------------- edge-parallel exp weights (no max shift) ------------------
__global__ void k_edgew1() {
    int e = blockIdx.x * blockDim.x + threadIdx.x;
    if (e >= ET) return;
    int2 cd = g_cd[e];
    float4 a = ((const float4*)g_as1)[cd.x];
    float4 b = ((const float4*)g_ad1)[cd.y];
    float4 w;
    w.x = __expf(lrelu(a.x + b.x));
    w.y = __expf(lrelu(a.y + b.y));
    w.z = __expf(lrelu(a.z + b.z));
    w.w = __expf(lrelu(a.w + b.w));
    ((float4*)g_w1)[e] = w;
}

__global__ void k_edgew2() {
    int e = blockIdx.x * blockDim.x + threadIdx.x;
    if (e >= ET) return;
    int2 cd = g_cd[e];
    g_w2[e] = __expf(lrelu(g_as2[cd.x] + g_ad2[cd.y]));
}

// ---------------- node aggregation, layer 1 (4 heads) -----------------------
__global__ void k_node1(const float* __restrict__ b1) {
    int w = (blockIdx.x * blockDim.x + threadIdx.x) >> 5;
    int lane = threadIdx.x & 31;
    if (w >= NN) return;
    int beg = g_rowptr[w], end = g_rowptr[w + 1];
    int hd = lane >> 3;

    float ws = 0.f;
    float4 acc = make_float4(0.f, 0.f, 0.f, 0.f);

    int i = beg;
    for (; i + 4 <= end; i += 4) {
        int s0 = g_cd[i].x, s1 = g_cd[i + 1].x, s2 = g_cd[i + 2].x, s3 = g_cd[i + 3].x;
        float4 w0 = ((const float4*)g_w1)[i];
        float4 w1 = ((const float4*)g_w1)[i + 1];
        float4 w2 = ((const float4*)g_w1)[i + 2];
        float4 w3 = ((const float4*)g_w1)[i + 3];
        uint2 r0 = ((const uint2*)g_h1)[s0 * 32 + lane];
        uint2 r1 = ((const uint2*)g_h1)[s1 * 32 + lane];
        uint2 r2 = ((const uint2*)g_h1)[s2 * 32 + lane];
        uint2 r3 = ((const uint2*)g_h1)[s3 * 32 + lane];
        float wh0 = (hd == 0) ? w0.x : (hd == 1) ? w0.y : (hd == 2) ? w0.z : w0.w;
        float wh1 = (hd == 0) ? w1.x : (hd == 1) ? w1.y : (hd == 2) ? w1.z : w1.w;
        float wh2 = (hd == 0) ? w2.x : (hd == 1) ? w2.y : (hd == 2) ? w2.z : w2.w;
        float wh3 = (hd == 0) ? w3.x : (hd == 1) ? w3.y : (hd == 2) ? w3.z : w3.w;
        ws += wh0 + wh1 + wh2 + wh3;
        float2 a0 = __half22float2(*reinterpret_cast<__half2*>(&r0.x));
        float2 b0 = __half22float2(*reinterpret_cast<__half2*>(&r0.y));
        float2 a1 = __half22float2(*reinterpret_cast<__half2*>(&r1.x));
        float2 b1v = __half22float2(*reinterpret_cast<__half2*>(&r1.y));
        float2 a2 = __half22float2(*reinterpret_cast<__half2*>(&r2.x));
        float2 b2v = __half22float2(*reinterpret_cast<__half2*>(&r2.y));
        float2 a3 = __half22float2(*reinterpret_cast<__half2*>(&r3.x));
        float2 b3v = __half22float2(*reinterpret_cast<__half2*>(&r3.y));
        acc.x += wh0 * a0.x + wh1 * a1.x + wh2 * a2.x + wh3 * a3.x;
        acc.y += wh0 * a0.y + wh1 * a1.y + wh2 * a2.y + wh3 * a3.y;
        acc.z += wh0 * b0.x + wh1 * b1v.x + wh2 * b2v.x + wh3 * b3v.x;
        acc.w += wh0 * b0.y + wh1 * b1v.y + wh2 * b2v.y + wh3 * b3v.y;
    }
    for (; i < end; i++) {
        int s = g_cd[i].x;
        float4 wv = ((const float4*)g_w1)[i];
        float wh = (hd == 0) ? wv.x : (hd == 1) ? wv.y : (hd == 2) ? wv.z : wv.w;
        ws += wh;
        uint2 raw = ((const uint2*)g_h1)[s * 32 + lane];
        float2 f01 = __half22float2(*reinterpret_cast<__half2*>(&raw.x));
        float2 f23 = __half22float2(*reinterpret_cast<__half2*>(&raw.y));
        acc.x += wh * f01.x;
        acc.y += wh * f01.y;
        acc.z += wh * f23.x;
        acc.w += wh * f23.y;
    }

    float inv = 1.f / (ws + 1e-16f);
    float4 bv = ((const float4*)b1)[lane];
    float4 o;
    o.x = elu(acc.x * inv + bv.x);
    o.y = elu(acc.y * inv + bv.y);
    o.z = elu(acc.z * inv + bv.z);
    o.w = elu(acc.w * inv + bv.w);
    ((float4*)g_agg1)[w * 32 + lane] = o;
}

// ---------------- node aggregation, layer 2 (1 head) ------------------------
__global__ void k_node2(const float* __restrict__ b2, float* __restrict__ out) {
    int w = (blockIdx.x * blockDim.x + threadIdx.x) >> 5;
    int lane = threadIdx.x & 31;
    if (w >= NN) return;
    int beg = g_rowptr[w], end = g_rowptr[w + 1];

    float ws = 0.f;
    float4 acc = make_float4(0.f, 0.f, 0.f, 0.f);

    int i = beg;
    for (; i + 4 <= end; i += 4) {
        int s0 = g_cd[i].x, s1 = g_cd[i + 1].x, s2 = g_cd[i + 2].x, s3 = g_cd[i + 3].x;
        float w0 = g_w2[i], w1 = g_w2[i + 1], w2 = g_w2[i + 2], w3 = g_w2[i + 3];
        uint2 r0 = ((const uint2*)g_h2)[s0 * 32 + lane];
        uint2 r1 = ((const uint2*)g_h2)[s1 * 32 + lane];
        uint2 r2 = ((const uint2*)g_h2)[s2 * 32 + lane];
        uint2 r3 = ((const uint2*)g_h2)[s3 * 32 + lane];
        ws += w0 + w1 + w2 + w3;
        float2 a0 = __half22float2(*reinterpret_cast<__half2*>(&r0.x));
        float2 b0 = __half22float2(*reinterpret_cast<__half2*>(&r0.y));
        float2 a1 = __half22float2(*reinterpret_cast<__half2*>(&r1.x));
        float2 b1v = __half22float2(*reinterpret_cast<__half2*>(&r1.y));
        float2 a2 = __half22float2(*reinterpret_cast<__half2*>(&r2.x));
        float2 b2v = __half22float2(*reinterpret_cast<__half2*>(&r2.y));
        float2 a3 = __half22float2(*reinterpret_cast<__half2*>(&r3.x));
        float2 b3v = __half22float2(*reinterpret_cast<__half2*>(&r3.y));
        acc.x += w0 * a0.x + w1 * a1.x + w2 * a2.x + w3 * a3.x;
        acc.y += w0 * a0.y + w1 * a1.y + w2 * a2.y + w3 * a3.y;
        acc.z += w0 * b0.x + w1 * b1v.x + w2 * b2v.x + w3 * b3v.x;
        acc.w += w0 * b0.y + w1 * b1v.y + w2 * b2v.y + w3 * b3v.y;
    }
    for (; i < end; i++) {
        int s = g_cd[i].x;
        float wv = g_w2[i];
        ws += wv;
        uint2 raw = ((const uint2*)g_h2)[s * 32 + lane];
        float2 f01 = __half22float2(*reinterpret_cast<__half2*>(&raw.x));
        float2 f23 = __half22float2(*reinterpret_cast<__half2*>(&raw.y));
        acc.x += wv * f01.x;
        acc.y += wv * f01.y;
        acc.z += wv * f23.x;
        acc.w += wv * f23.y;
    }

    float inv = 1.f / (ws + 1e-16f);
    float4 bv = ((const float4*)b2)[lane];
    float4 o;
    o.x = elu(acc.x * inv + bv.x);
    o.y = elu(acc.y * inv + bv.y);
    o.z = elu(acc.z * inv + bv.z);
    o.w = elu(acc.w * inv + bv.w);
    ((float4*)out)[w * 32 + lane] = o;
}

// ---------------- host launch ------------------------------------------------
extern "C" void kernel_launch(void* const* d_in, const int* in_sizes, int n_in,
                              void* d_out, int out_size) {
    const float* x    = (const float*)d_in[0];
    const int*   ei   = (const int*)  d_in[1];
    const float* W1   = (const float*)d_in[2];
    const float* a_s1 = (const float*)d_in[3];
    const float* a_d1 = (const float*)d_in[4];
    const float* b1   = (const float*)d_in[5];
    const float* W2   = (const float*)d_in[6];
    const float* a_s2 = (const float*)d_in[7];
    const float* a_d2 = (const float*)d_in[8];
    const float* b2   = (const float*)d_in[9];
    float* out = (float*)d_out;

    const int EB = (ET + 255) / 256;
    const int NB = (NN + 255) / 256;
    const int WARPB = (NN * 32 + 255) / 256;
    const int GB = (NN + 63) / 64;

    // fork: CSR build on s1, GEMM1 on the capture-origin (default) stream.
    // kernel_launch runs only twice (correctness + capture), so per-call
    // stream/event creation without destroy is bounded and allocation-free
    // on the device side.
    cudaStream_t s1;
    cudaEvent_t evFork, evJoin;
    cudaStreamCreateWithFlags(&s1, cudaStreamNonBlocking);
    cudaEventCreateWithFlags(&evFork, cudaEventDisableTiming);
    cudaEventCreateWithFlags(&evJoin, cudaEventDisableTiming);

    cudaEventRecord(evFork, 0);
    cudaStreamWaitEvent(s1, evFork, 0);

    // CSR chain on s1
    k_zero<<<NB, 256, 0, s1>>>();
    k_count<<<EB, 256, 0, s1>>>(ei);
    k_scan_part<<<SCAN_B, 1024, 0, s1>>>();
    k_scan_top<<<1, 64, 0, s1>>>();
    k_rowptr<<<NB, 256, 0, s1>>>();
    k_fill<<<EB, 256, 0, s1>>>(ei);
    cudaEventRecord(evJoin, s1);

    // GEMM1 on default stream (independent of CSR)
    k_gemm<0><<<GB, 256>>>(x, W1, a_s1, a_d1);

    // join: remaining chain needs both
    cudaStreamWaitEvent(0, evJoin, 0);

    k_edgew1<<<EB, 256>>>();
    k_node1<<<WARPB, 256>>>(b1);

    k_gemm<1><<<GB, 256>>>(nullptr, W2, a_s2, a_d2);
    k_edgew2<<<EB, 256>>>();
    k_node2<<<WARPB, 256>>>(b2, out);
}

// round 12
// speedup vs baseline: 1.5049x; 1.3315x over previous
#include <cuda_runtime.h>
#include <cuda_fp16.h>
#include <mma.h>
#include <math.h>
#include <float.h>

using namespace nvcuda;

#define NN 50000
#define EE 800000
#define ET (EE + NN)
#define SCAN_B 49   // ceil(50000/1024)

#define SA_LD 136   // padded half stride (64 rows)
#define SW_LD 136   // padded half stride (128 rows)
#define SC_LD 132   // padded float stride (64 rows)
#define GEMM_SMEM (64 * SA_LD * 2 + 128 * SW_LD * 2)   // 52224 B

// ---------------- scratch ---------------------------------------------------
__device__ __half g_h1[NN * 128];
__device__ __half g_h2[NN * 128];
__device__ float  g_agg1[NN * 128];
__device__ float  g_as1[NN * 4];
__device__ float  g_ad1[NN * 4];
__device__ float  g_as2[NN];
__device__ float  g_ad2[NN];
__device__ int    g_deg[NN];           // zero at load; re-zeroed by k_scan_part
__device__ int    g_scan[SCAN_B * 1024];   // inclusive within block
__device__ int    g_scan2[SCAN_B * 1024];  // exclusive within block
__device__ int    g_bsum[SCAN_B];
__device__ int    g_rowptr[NN + 1];
__device__ int    g_fill[NN];
__device__ int2   g_cd[ET];            // packed (src, dst)
__device__ float  g_w1[ET * 4];        // per-edge exp weights, layer1
__device__ float  g_w2[ET];            // layer2

__device__ __forceinline__ float lrelu(float x) { return x > 0.f ? x : 0.2f * x; }
__device__ __forceinline__ float elu(float x)   { return x > 0.f ? x : expm1f(x); }

// ---------------- CSR build -------------------------------------------------
__global__ void k_count(const int* __restrict__ ei) {
    int e = blockIdx.x * blockDim.x + threadIdx.x;
    if (e >= ET) return;
    int d = (e < EE) ? ei[EE + e] : (e - EE);
    atomicAdd(&g_deg[d], 1);
}

// per-1024 block scan; also re-zeroes g_deg (maintains deg==0 invariant)
__global__ void k_scan_part() {
    __shared__ int sh[1024];
    int tid = threadIdx.x;
    int i = blockIdx.x * 1024 + tid;
    int v = (i < NN) ? g_deg[i] : 0;
    sh[tid] = v;
    __syncthreads();
#pragma unroll
    for (int off = 1; off < 1024; off <<= 1) {
        int t = (tid >= off) ? sh[tid - off] : 0;
        __syncthreads();
        sh[tid] += t;
        __syncthreads();
    }
    g_scan[i]  = sh[tid];
    g_scan2[i] = sh[tid] - v;
    if (i < NN) g_deg[i] = 0;
    if (tid == 1023) g_bsum[blockIdx.x] = sh[tid];
}

// rowptr + fill-base; block-local redundant top-level prefix over g_bsum
__global__ void k_rowptr() {
    __shared__ int sb[SCAN_B + 1];
    int t = threadIdx.x;
    if (t < SCAN_B) sb[t + 1] = g_bsum[t];
    __syncthreads();
    if (t == 0) {
        sb[0] = 0;
        for (int b = 1; b < SCAN_B; b++) sb[b] += sb[b - 1];
    }
    __syncthreads();
    int i = blockIdx.x * blockDim.x + t;
    if (i >= NN) return;
    int boff = sb[i >> 10];
    g_rowptr[i + 1] = g_scan[i] + boff;
    g_fill[i] = g_scan2[i] + boff;
    if (i == 0) g_rowptr[0] = 0;
}

__global__ void k_fill(const int* __restrict__ ei) {
    int e = blockIdx.x * blockDim.x + threadIdx.x;
    if (e >= ET) return;
    int s, d;
    if (e < EE) { s = ei[e]; d = ei[EE + e]; } else { s = e - EE; d = s; }
    int pos = atomicAdd(&g_fill[d], 1);
    g_cd[pos] = make_int2(s, d);
}

// ---------------- tensor-core GEMM [NN,128]@[128,128], padded smem ----------
// 512 threads, 64 rows x 128 cols per block. fp32 inputs converted to fp16 in
// staging; fp32 accumulate; fused fp16 H store + alpha epilogue.
template <int LAYER>
__global__ void __launch_bounds__(512) k_gemm_tc(const float* __restrict__ Xext,
                                                 const float* __restrict__ W,
                                                 const float* __restrict__ asrc,
                                                 const float* __restrict__ adst) {
    extern __shared__ __align__(16) char smem[];
    __half* sA = (__half*)smem;                        // 64 x SA_LD
    __half* sW = (__half*)(smem + 64 * SA_LD * 2);     // 128 x SW_LD
    float*  sC = (float*)smem;                         // 64 x SC_LD (reuse)

    const float* __restrict__ X = (LAYER == 0) ? Xext : g_agg1;
    __half* __restrict__ H = (LAYER == 0) ? g_h1 : g_h2;

    int tid = threadIdx.x;
    int row0 = blockIdx.x * 64;

    // stage W (fp32 -> fp16): 128x128 = 4096 float4, 8 per thread
#pragma unroll
    for (int j = 0; j < 8; j++) {
        int idx = tid + j * 512;
        int r = idx >> 5, c4 = idx & 31;
        float4 v = ((const float4*)W)[idx];
        __half2 h0 = __floats2half2_rn(v.x, v.y);
        __half2 h1 = __floats2half2_rn(v.z, v.w);
        *(__half2*)(sW + r * SW_LD + c4 * 4)     = h0;
        *(__half2*)(sW + r * SW_LD + c4 * 4 + 2) = h1;
    }
    // stage A (fp32 -> fp16): 64x128 = 2048 float4, 4 per thread
#pragma unroll
    for (int j = 0; j < 4; j++) {
        int idx = tid + j * 512;
        int r = idx >> 5, c4 = idx & 31;
        int row = row0 + r;
        float4 v = make_float4(0.f, 0.f, 0.f, 0.f);
        if (row < NN) v = ((const float4*)X)[row * 32 + c4];
        __half2 h0 = __floats2half2_rn(v.x, v.y);
        __half2 h1 = __floats2half2_rn(v.z, v.w);
        *(__half2*)(sA + r * SA_LD + c4 * 4)     = h0;
        *(__half2*)(sA + r * SA_LD + c4 * 4 + 2) = h1;
    }
    __syncthreads();

    // MMA: warp (wr, wc) -> rows [wr*16,+16), cols [wc*32,+32)
    int wid = tid >> 5;
    int wr = wid >> 2, wc = wid & 3;

    wmma::fragment<wmma::accumulator, 16, 16, 16, float> c0, c1;
    wmma::fill_fragment(c0, 0.f);
    wmma::fill_fragment(c1, 0.f);

#pragma unroll
    for (int k = 0; k < 8; k++) {
        wmma::fragment<wmma::matrix_a, 16, 16, 16, __half, wmma::row_major> af;
        wmma::fragment<wmma::matrix_b, 16, 16, 16, __half, wmma::row_major> bf0, bf1;
        wmma::load_matrix_sync(af, sA + wr * 16 * SA_LD + k * 16, SA_LD);
        wmma::load_matrix_sync(bf0, sW + k * 16 * SW_LD + wc * 32, SW_LD);
        wmma::load_matrix_sync(bf1, sW + k * 16 * SW_LD + wc * 32 + 16, SW_LD);
        wmma::mma_sync(c0, af, bf0, c0);
        wmma::mma_sync(c1, af, bf1, c1);
    }
    __syncthreads();   // done with sA/sW; reuse as sC

    wmma::store_matrix_sync(sC + wr * 16 * SC_LD + wc * 32,      c0, SC_LD, wmma::mem_row_major);
    wmma::store_matrix_sync(sC + wr * 16 * SC_LD + wc * 32 + 16, c1, SC_LD, wmma::mem_row_major);
    __syncthreads();

    // epilogue: 8 threads per row, 16 cols each
    {
        int r = tid >> 3;
        int t8 = tid & 7;
        int c0i = t8 * 16;
        int row = row0 + r;
        if (row < NN) {
            float v[16];
#pragma unroll
            for (int j = 0; j < 16; j++) v[j] = sC[r * SC_LD + c0i + j];

            __half2 hh[8];
#pragma unroll
            for (int j = 0; j < 8; j++) hh[j] = __floats2half2_rn(v[2 * j], v[2 * j + 1]);
            uint4 p0 = make_uint4(*(unsigned*)&hh[0], *(unsigned*)&hh[1], *(unsigned*)&hh[2], *(unsigned*)&hh[3]);
            uint4 p1 = make_uint4(*(unsigned*)&hh[4], *(unsigned*)&hh[5], *(unsigned*)&hh[6], *(unsigned*)&hh[7]);
            ((uint4*)H)[row * 16 + t8 * 2]     = p0;
            ((uint4*)H)[row * 16 + t8 * 2 + 1] = p1;

            float s = 0.f, d = 0.f;
#pragma unroll
            for (int j = 0; j < 16; j++) {
                s += v[j] * asrc[c0i + j];
                d += v[j] * adst[c0i + j];
            }
            if (LAYER == 0) {
                s += __shfl_xor_sync(0xffffffffu, s, 1);
                d += __shfl_xor_sync(0xffffffffu, d, 1);
                if ((t8 & 1) == 0) {
                    g_as1[row * 4 + (t8 >> 1)] = s;
                    g_ad1[row * 4 + (t8 >> 1)] = d;
                }
            } else {
#pragma unroll
                for (int off = 1; off < 8; off <<= 1) {
                    s += __shfl_xor_sync(0xffffffffu, s, off);
                    d += __shfl_xor_sync(0xffffffffu, d, off);
                }
                if (t8 == 0) { g_as2[row] = s; g_ad2[row] = d; }
            }
        }
    }
}

// ---------------- edge-parallel exp weights (no max shift) ------------------
__global__ void k_edgew1() {
    int e = blockIdx.x * blockDim.x + threadIdx.x;
    if (e >= ET) return;
    int2 cd = g_cd[e];
    float4 a = ((const float4*)g_as1)[cd.x];
    float4 b = ((const float4*)g_ad1)[cd.y];
    float4 w;
    w.x = __expf(lrelu(a.x + b.x));
    w.y = __expf(lrelu(a.y + b.y));
    w.z = __expf(lrelu(a.z + b.z));
    w.w = __expf(lrelu(a.w + b.w));
    ((float4*)g_w1)[e] = w;
}

__global__ void k_edgew2() {
    int e = blockIdx.x * blockDim.x + threadIdx.x;
    if (e >= ET) return;
    int2 cd = g_cd[e];
    g_w2[e] = __expf(lrelu(g_as2[cd.x] + g_ad2[cd.y]));
}

// ---------------- node aggregation, layer 1 (4 heads) -----------------------
__global__ void k_node1(const float* __restrict__ b1) {
    int w = (blockIdx.x * blockDim.x + threadIdx.x) >> 5;
    int lane = threadIdx.x & 31;
    if (w >= NN) return;
    int beg = g_rowptr[w], end = g_rowptr[w + 1];
    int hd = lane >> 3;

    float ws = 0.f;
    float4 acc = make_float4(0.f, 0.f, 0.f, 0.f);

    int i = beg;
    for (; i + 4 <= end; i += 4) {
        int s0 = g_cd[i].x, s1 = g_cd[i + 1].x, s2 = g_cd[i + 2].x, s3 = g_cd[i + 3].x;
        float4 w0 = ((const float4*)g_w1)[i];
        float4 w1 = ((const float4*)g_w1)[i + 1];
        float4 w2 = ((const float4*)g_w1)[i + 2];
        float4 w3 = ((const float4*)g_w1)[i + 3];
        uint2 r0 = ((const uint2*)g_h1)[s0 * 32 + lane];
        uint2 r1 = ((const uint2*)g_h1)[s1 * 32 + lane];
        uint2 r2 = ((const uint2*)g_h1)[s2 * 32 + lane];
        uint2 r3 = ((const uint2*)g_h1)[s3 * 32 + lane];
        float wh0 = (hd == 0) ? w0.x : (hd == 1) ? w0.y : (hd == 2) ? w0.z : w0.w;
        float wh1 = (hd == 0) ? w1.x : (hd == 1) ? w1.y : (hd == 2) ? w1.z : w1.w;
        float wh2 = (hd == 0) ? w2.x : (hd == 1) ? w2.y : (hd == 2) ? w2.z : w2.w;
        float wh3 = (hd == 0) ? w3.x : (hd == 1) ? w3.y : (hd == 2) ? w3.z : w3.w;
        ws += wh0 + wh1 + wh2 + wh3;
        float2 a0 = __half22float2(*reinterpret_cast<__half2*>(&r0.x));
        float2 b0 = __half22float2(*reinterpret_cast<__half2*>(&r0.y));
        float2 a1 = __half22float2(*reinterpret_cast<__half2*>(&r1.x));
        float2 b1v = __half22float2(*reinterpret_cast<__half2*>(&r1.y));
        float2 a2 = __half22float2(*reinterpret_cast<__half2*>(&r2.x));
        float2 b2v = __half22float2(*reinterpret_cast<__half2*>(&r2.y));
        float2 a3 = __half22float2(*reinterpret_cast<__half2*>(&r3.x));
        float2 b3v = __half22float2(*reinterpret_cast<__half2*>(&r3.y));
        acc.x += wh0 * a0.x + wh1 * a1.x + wh2 * a2.x + wh3 * a3.x;
        acc.y += wh0 * a0.y + wh1 * a1.y + wh2 * a2.y + wh3 * a3.y;
        acc.z += wh0 * b0.x + wh1 * b1v.x + wh2 * b2v.x + wh3 * b3v.x;
        acc.w += wh0 * b0.y + wh1 * b1v.y + wh2 * b2v.y + wh3 * b3v.y;
    }
    for (; i < end; i++) {
        int s = g_cd[i].x;
        float4 wv = ((const float4*)g_w1)[i];
        float wh = (hd == 0) ? wv.x : (hd == 1) ? wv.y : (hd == 2) ? wv.z : wv.w;
        ws += wh;
        uint2 raw = ((const uint2*)g_h1)[s * 32 + lane];
        float2 f01 = __half22float2(*reinterpret_cast<__half2*>(&raw.x));
        float2 f23 = __half22float2(*reinterpret_cast<__half2*>(&raw.y));
        acc.x += wh * f01.x;
        acc.y += wh * f01.y;
        acc.z += wh * f23.x;
        acc.w += wh * f23.y;
    }

    float inv = 1.f / (ws + 1e-16f);
    float4 bv = ((const float4*)b1)[lane];
    float4 o;
    o.x = elu(acc.x * inv + bv.x);
    o.y = elu(acc.y * inv + bv.y);
    o.z = elu(acc.z * inv + bv.z);
    o.w = elu(acc.w * inv + bv.w);
    ((float4*)g_agg1)[w * 32 + lane] = o;
}

// ---------------- node aggregation, layer 2 (1 head) ------------------------
__global__ void k_node2(const float* __restrict__ b2, float* __restrict__ out) {
    int w = (blockIdx.x * blockDim.x + threadIdx.x) >> 5;
    int lane = threadIdx.x & 31;
    if (w >= NN) return;
    int beg = g_rowptr[w], end = g_rowptr[w + 1];

    float ws = 0.f;
    float4 acc = make_float4(0.f, 0.f, 0.f, 0.f);

    int i = beg;
    for (; i + 4 <= end; i += 4) {
        int s0 = g_cd[i].x, s1 = g_cd[i + 1].x, s2 = g_cd[i + 2].x, s3 = g_cd[i + 3].x;
        float w0 = g_w2[i], w1 = g_w2[i + 1], w2 = g_w2[i + 2], w3 = g_w2[i + 3];
        uint2 r0 = ((const uint2*)g_h2)[s0 * 32 + lane];
        uint2 r1 = ((const uint2*)g_h2)[s1 * 32 + lane];
        uint2 r2 = ((const uint2*)g_h2)[s2 * 32 + lane];
        uint2 r3 = ((const uint2*)g_h2)[s3 * 32 + lane];
        ws += w0 + w1 + w2 + w3;
        float2 a0 = __half22float2(*reinterpret_cast<__half2*>(&r0.x));
        float2 b0 = __half22float2(*reinterpret_cast<__half2*>(&r0.y));
        float2 a1 = __half22float2(*reinterpret_cast<__half2*>(&r1.x));
        float2 b1v = __half22float2(*reinterpret_cast<__half2*>(&r1.y));
        float2 a2 = __half22float2(*reinterpret_cast<__half2*>(&r2.x));
        float2 b2v = __half22float2(*reinterpret_cast<__half2*>(&r2.y));
        float2 a3 = __half22float2(*reinterpret_cast<__half2*>(&r3.x));
        float2 b3v = __half22float2(*reinterpret_cast<__half2*>(&r3.y));
        acc.x += w0 * a0.x + w1 * a1.x + w2 * a2.x + w3 * a3.x;
        acc.y += w0 * a0.y + w1 * a1.y + w2 * a2.y + w3 * a3.y;
        acc.z += w0 * b0.x + w1 * b1v.x + w2 * b2v.x + w3 * b3v.x;
        acc.w += w0 * b0.y + w1 * b1v.y + w2 * b2v.y + w3 * b3v.y;
    }
    for (; i < end; i++) {
        int s = g_cd[i].x;
        float wv = g_w2[i];
        ws += wv;
        uint2 raw = ((const uint2*)g_h2)[s * 32 + lane];
        float2 f01 = __half22float2(*reinterpret_cast<__half2*>(&raw.x));
        float2 f23 = __half22float2(*reinterpret_cast<__half2*>(&raw.y));
        acc.x += wv * f01.x;
        acc.y += wv * f01.y;
        acc.z += wv * f23.x;
        acc.w += wv * f23.y;
    }

    float inv = 1.f / (ws + 1e-16f);
    float4 bv = ((const float4*)b2)[lane];
    float4 o;
    o.x = elu(acc.x * inv + bv.x);
    o.y = elu(acc.y * inv + bv.y);
    o.z = elu(acc.z * inv + bv.z);
    o.w = elu(acc.w * inv + bv.w);
    ((float4*)out)[w * 32 + lane] = o;
}

// ---------------- host launch ------------------------------------------------
extern "C" void kernel_launch(void* const* d_in, const int* in_sizes, int n_in,
                              void* d_out, int out_size) {
    const float* x    = (const float*)d_in[0];
    const int*   ei   = (const int*)  d_in[1];
    const float* W1   = (const float*)d_in[2];
    const float* a_s1 = (const float*)d_in[3];
    const float* a_d1 = (const float*)d_in[4];
    const float* b1   = (const float*)d_in[5];
    const float* W2   = (const float*)d_in[6];
    const float* a_s2 = (const float*)d_in[7];
    const float* a_d2 = (const float*)d_in[8];
    const float* b2   = (const float*)d_in[9];
    float* out = (float*)d_out;

    const int EB = (ET + 255) / 256;
    const int NB = (NN + 255) / 256;
    const int WARPB = (NN * 32 + 255) / 256;
    const int GB = (NN + 63) / 64;

    cudaFuncSetAttribute(k_gemm_tc<0>, cudaFuncAttributeMaxDynamicSharedMemorySize, GEMM_SMEM);
    cudaFuncSetAttribute(k_gemm_tc<1>, cudaFuncAttributeMaxDynamicSharedMemorySize, GEMM_SMEM);

    // fork: CSR build on s1, GEMM1 on default stream
    cudaStream_t s1;
    cudaEvent_t evFork, evJoin;
    cudaStreamCreateWithFlags(&s1, cudaStreamNonBlocking);
    cudaEventCreateWithFlags(&evFork, cudaEventDisableTiming);
    cudaEventCreateWithFlags(&evJoin, cudaEventDisableTiming);

    cudaEventRecord(evFork, 0);
    cudaStreamWaitEvent(s1, evFork, 0);

    // CSR chain on s1 (g_deg zeroed invariant: load-time + re-zero in scan_part)
    k_count<<<EB, 256, 0, s1>>>(ei);
    k_scan_part<<<SCAN_B, 1024, 0, s1>>>();
    k_rowptr<<<NB, 256, 0, s1>>>();
    k_fill<<<EB, 256, 0, s1>>>(ei);
    cudaEventRecord(evJoin, s1);

    // GEMM1 on default stream (independent of CSR)
    k_gemm_tc<0><<<GB, 512, GEMM_SMEM>>>(x, W1, a_s1, a_d1);

    // join
    cudaStreamWaitEvent(0, evJoin, 0);

    k_edgew1<<<EB, 256>>>();
    k_node1<<<WARPB, 256>>>(b1);

    k_gemm_tc<1><<<GB, 512, GEMM_SMEM>>>(nullptr, W2, a_s2, a_d2);
    k_edgew2<<<EB, 256>>>();
    k_node2<<<WARPB, 256>>>(b2, out);
}